// round 2
// baseline (speedup 1.0000x reference)
#include <cuda_runtime.h>
#include <math.h>

#define N_NODES 4096
#define IN_F    256
#define NH      4
#define HD      64
#define HID     256   // NH*HD

// ---------------- scratch (device globals; no allocs allowed) ----------------
__device__ float g_h[N_NODES * HID];        // 4 MB: h = x @ W
__device__ float g_s1[NH * N_NODES];        // si  [h][n]
__device__ float g_s2[NH * N_NODES];        // sj  [h][n]
__device__ float g_e1i[NH * N_NODES];       // exp(si)
__device__ float g_e2i[NH * N_NODES];       // exp(0.2*si)
__device__ float g_e1j[NH * N_NODES];       // exp(sj)
__device__ float g_e2j[NH * N_NODES];       // exp(0.2*sj)

// ---------------- kernel A: h = x @ W  (4096x256 @ 256x256) ----------------
__global__ __launch_bounds__(256) void gemm_hw(const float* __restrict__ A,
                                               const float* __restrict__ B,
                                               float* __restrict__ C) {
    __shared__ float As[16][65];  // As[k][m]
    __shared__ float Bs[16][65];  // Bs[k][n]
    int tx = threadIdx.x;
    int bm = blockIdx.x * 64;
    int bn = blockIdx.y * 64;
    int tm = (tx >> 4) * 4;
    int tn = (tx & 15) * 4;
    float acc[4][4] = {};
    for (int k0 = 0; k0 < 256; k0 += 16) {
        #pragma unroll
        for (int l = 0; l < 4; l++) {
            int idx = tx + l * 256;          // 0..1023
            int m = idx >> 4, k = idx & 15;
            As[k][m] = A[(bm + m) * 256 + k0 + k];
        }
        {
            int k = tx >> 6, n = tx & 63;
            #pragma unroll
            for (int l = 0; l < 4; l++)
                Bs[k + l * 4][n] = B[(k0 + k + l * 4) * 256 + bn + n];
        }
        __syncthreads();
        #pragma unroll
        for (int k = 0; k < 16; k++) {
            float a[4], b[4];
            #pragma unroll
            for (int u = 0; u < 4; u++) a[u] = As[k][tm + u];
            #pragma unroll
            for (int v = 0; v < 4; v++) b[v] = Bs[k][tn + v];
            #pragma unroll
            for (int u = 0; u < 4; u++)
                #pragma unroll
                for (int v = 0; v < 4; v++) acc[u][v] += a[u] * b[v];
        }
        __syncthreads();
    }
    #pragma unroll
    for (int u = 0; u < 4; u++)
        #pragma unroll
        for (int v = 0; v < 4; v++)
            C[(bm + tm + u) * 256 + bn + tn + v] = acc[u][v];
}

// ---------------- kernel B: scores + factorized exponentials ----------------
// one warp per (node, head): si = <h_i, a1>, sj = <h_i, a2>
__global__ __launch_bounds__(256) void scores_kernel(const float* __restrict__ a1,
                                                     const float* __restrict__ a2) {
    int warp = (blockIdx.x * blockDim.x + threadIdx.x) >> 5;
    int lane = threadIdx.x & 31;
    if (warp >= N_NODES * NH) return;
    int node = warp >> 2, head = warp & 3;
    const float* hp = g_h + node * HID + head * HD;
    float v0 = hp[lane], v1 = hp[lane + 32];
    float s1 = v0 * a1[lane] + v1 * a1[lane + 32];
    float s2 = v0 * a2[lane] + v1 * a2[lane + 32];
    #pragma unroll
    for (int o = 16; o > 0; o >>= 1) {
        s1 += __shfl_xor_sync(0xffffffffu, s1, o);
        s2 += __shfl_xor_sync(0xffffffffu, s2, o);
    }
    if (lane == 0) {
        int idx = head * N_NODES + node;
        g_s1[idx]  = s1;
        g_s2[idx]  = s2;
        g_e1i[idx] = __expf(s1);
        g_e2i[idx] = __expf(0.2f * s1);
        g_e1j[idx] = __expf(s2);
        g_e2j[idx] = __expf(0.2f * s2);
    }
}

// ---------------- kernel C: fused masked-softmax aggregation ----------------
// Each block handles G=16 destination rows i. For each chunk of CJ=128 source
// nodes j: phase 1 builds w[g][j'][h] (factorized exp weights, adj-masked) in
// shared; phase 2: thread t=(h*64+d) accumulates acc[g] += w * h[j, h*64+d].
#define G  16
#define CJ 128

__global__ __launch_bounds__(256) void attn_kernel(const int* __restrict__ adj,
                                                   float* __restrict__ out) {
    __shared__ float wsh[CJ * G * NH];   // [j'][g][h]  = 32 KB
    __shared__ float denomsh[G * NH];

    int t  = threadIdx.x;
    int i0 = blockIdx.x * G;

    // phase-2 identity: column of h (h2 = head)
    int h2 = t >> 6;
    // phase-1 identity: (g1, h1) fixed per thread; jlane covers j' range
    int gh    = t & 63;
    int g1    = gh >> 2;
    int h1    = gh & 3;
    int jlane = t >> 6;  // 0..3

    float s1i = g_s1 [h1 * N_NODES + i0 + g1];
    float e1i = g_e1i[h1 * N_NODES + i0 + g1];
    float e2i = g_e2i[h1 * N_NODES + i0 + g1];

    float dpart = 0.f;
    float acc[G];
    #pragma unroll
    for (int g = 0; g < G; g++) acc[g] = 0.f;
    if (t < G * NH) denomsh[t] = 0.f;

    const long adjrow = (long)(i0 + g1) * N_NODES;

    for (int j0 = 0; j0 < N_NODES; j0 += CJ) {
        // ---- phase 1: weights for this chunk ----
        #pragma unroll 1
        for (int k = 0; k < 8; k++) {
            int jp = jlane * 32 + k * 4;
            int j  = j0 + jp;
            int4   av  = *(const int4*)  (adj   + adjrow + j);
            float4 s2v = *(const float4*)(g_s2  + h1 * N_NODES + j);
            float4 e1v = *(const float4*)(g_e1j + h1 * N_NODES + j);
            float4 e2v = *(const float4*)(g_e2j + h1 * N_NODES + j);
            float w0 = (av.x > 0) ? ((s1i + s2v.x > 0.f) ? e1i * e1v.x : e2i * e2v.x) : 0.f;
            float w1 = (av.y > 0) ? ((s1i + s2v.y > 0.f) ? e1i * e1v.y : e2i * e2v.y) : 0.f;
            float w2 = (av.z > 0) ? ((s1i + s2v.z > 0.f) ? e1i * e1v.z : e2i * e2v.z) : 0.f;
            float w3 = (av.w > 0) ? ((s1i + s2v.w > 0.f) ? e1i * e1v.w : e2i * e2v.w) : 0.f;
            wsh[(jp + 0) * (G * NH) + gh] = w0;
            wsh[(jp + 1) * (G * NH) + gh] = w1;
            wsh[(jp + 2) * (G * NH) + gh] = w2;
            wsh[(jp + 3) * (G * NH) + gh] = w3;
            dpart += (w0 + w1) + (w2 + w3);
        }
        __syncthreads();

        // ---- phase 2: aggregate (coalesced h reads, broadcast LDS) ----
        const float* hrow = g_h + (size_t)j0 * HID + t;
        #pragma unroll 4
        for (int jp = 0; jp < CJ; jp++) {
            float hv = hrow[(size_t)jp * HID];
            #pragma unroll
            for (int g = 0; g < G; g++)
                acc[g] += wsh[jp * (G * NH) + g * NH + h2] * hv;
        }
        __syncthreads();
    }

    atomicAdd(&denomsh[g1 * NH + h1], dpart);
    __syncthreads();

    #pragma unroll
    for (int g = 0; g < G; g++)
        out[(size_t)(i0 + g) * HID + t] = acc[g] / denomsh[g * NH + h2];
}

// ---------------- launch ----------------
extern "C" void kernel_launch(void* const* d_in, const int* in_sizes, int n_in,
                              void* d_out, int out_size) {
    const float* x   = (const float*)d_in[0];   // [4096, 256]
    const int*   adj = (const int*)  d_in[1];   // [4096, 4096]
    const float* W   = (const float*)d_in[2];   // [256, 256]
    const float* a1  = (const float*)d_in[3];   // [64]
    const float* a2  = (const float*)d_in[4];   // [64]
    float* out = (float*)d_out;                 // [4096, 256]

    float* h_ptr;
    cudaGetSymbolAddress((void**)&h_ptr, g_h);

    dim3 ggrid(N_NODES / 64, HID / 64);
    gemm_hw<<<ggrid, 256>>>(x, W, h_ptr);

    scores_kernel<<<(N_NODES * NH * 32) / 256, 256>>>(a1, a2);

    attn_kernel<<<N_NODES / G, 256>>>(adj, out);
}

// round 5
// speedup vs baseline: 3.0525x; 3.0525x over previous
#include <cuda_runtime.h>
#include <math.h>

#define N_NODES 4096
#define IN_F    256
#define NH      4
#define HD      64
#define HID     256   // NH*HD

// ---------------- scratch (device globals; no allocs allowed) ----------------
__device__ float g_h[N_NODES * HID];        // 4 MB: h = x @ W
__device__ float g_s1[NH * N_NODES];        // si  [h][n]
__device__ float g_s2[NH * N_NODES];        // sj  [h][n]
__device__ float g_e1i[NH * N_NODES];       // exp(si)
__device__ float g_e2i[NH * N_NODES];       // exp(0.2*si)
__device__ float g_e1j[NH * N_NODES];       // exp(sj)
__device__ float g_e2j[NH * N_NODES];       // exp(0.2*sj)

// ---------------- kernel A: h = x @ W  (4096x256 @ 256x256) ----------------
__global__ __launch_bounds__(256) void gemm_hw(const float* __restrict__ A,
                                               const float* __restrict__ B,
                                               float* __restrict__ C) {
    __shared__ float As[16][65];  // As[k][m]
    __shared__ float Bs[16][65];  // Bs[k][n]
    int tx = threadIdx.x;
    int bm = blockIdx.x * 64;
    int bn = blockIdx.y * 64;
    int tm = (tx >> 4) * 4;
    int tn = (tx & 15) * 4;
    float acc[4][4] = {};
    for (int k0 = 0; k0 < 256; k0 += 16) {
        #pragma unroll
        for (int l = 0; l < 4; l++) {
            int idx = tx + l * 256;          // 0..1023
            int m = idx >> 4, k = idx & 15;
            As[k][m] = A[(bm + m) * 256 + k0 + k];
        }
        {
            int k = tx >> 6, n = tx & 63;
            #pragma unroll
            for (int l = 0; l < 4; l++)
                Bs[k + l * 4][n] = B[(k0 + k + l * 4) * 256 + bn + n];
        }
        __syncthreads();
        #pragma unroll
        for (int k = 0; k < 16; k++) {
            float a[4], b[4];
            #pragma unroll
            for (int u = 0; u < 4; u++) a[u] = As[k][tm + u];
            #pragma unroll
            for (int v = 0; v < 4; v++) b[v] = Bs[k][tn + v];
            #pragma unroll
            for (int u = 0; u < 4; u++)
                #pragma unroll
                for (int v = 0; v < 4; v++) acc[u][v] += a[u] * b[v];
        }
        __syncthreads();
    }
    #pragma unroll
    for (int u = 0; u < 4; u++)
        #pragma unroll
        for (int v = 0; v < 4; v++)
            C[(bm + tm + u) * 256 + bn + tn + v] = acc[u][v];
}

// ---------------- kernel B: scores + factorized exponentials ----------------
__global__ __launch_bounds__(256) void scores_kernel(const float* __restrict__ a1,
                                                     const float* __restrict__ a2) {
    int warp = (blockIdx.x * blockDim.x + threadIdx.x) >> 5;
    int lane = threadIdx.x & 31;
    if (warp >= N_NODES * NH) return;
    int node = warp >> 2, head = warp & 3;
    const float* hp = g_h + node * HID + head * HD;
    float v0 = hp[lane], v1 = hp[lane + 32];
    float s1 = v0 * a1[lane] + v1 * a1[lane + 32];
    float s2 = v0 * a2[lane] + v1 * a2[lane + 32];
    #pragma unroll
    for (int o = 16; o > 0; o >>= 1) {
        s1 += __shfl_xor_sync(0xffffffffu, s1, o);
        s2 += __shfl_xor_sync(0xffffffffu, s2, o);
    }
    if (lane == 0) {
        int idx = head * N_NODES + node;
        g_s1[idx]  = s1;
        g_s2[idx]  = s2;
        g_e1i[idx] = __expf(s1);
        g_e2i[idx] = __expf(0.2f * s1);
        g_e1j[idx] = __expf(s2);
        g_e2j[idx] = __expf(0.2f * s2);
    }
}

// ---------------- kernel C: flash-style masked softmax-agg via tf32 MMA -----
// Block = (64 dest rows, 1 head). Loop j in 64-chunks: build tf32-quantized
// weight tile P[64][64] + fp32 row denominators, load V tile (rna-rounded),
// mma.sync.m16n8k8.tf32 accumulate in fp32 regs. Normalize at the end.
#define TM  64
#define TJ  64
#define PST 68   // P smem stride (A-frag LDS conflict-free)
#define VST 72   // V smem stride (B-frag LDS conflict-free)

__device__ __forceinline__ unsigned f2tf32(float f) {
    unsigned r;
    asm("cvt.rna.tf32.f32 %0, %1;" : "=r"(r) : "f"(f));
    return r;
}

__global__ __launch_bounds__(256) void attn_mma(const int* __restrict__ adj,
                                                float* __restrict__ out) {
    __shared__ float Psh[TM * PST];
    __shared__ float Vsh[TJ * VST];
    __shared__ float dsh[TM];

    int t    = threadIdx.x;
    int lane = t & 31;
    int warp = t >> 5;
    int i0   = blockIdx.x * TM;
    int head = blockIdx.y;

    // P-build identity: row m, column-quarter q
    int m = t >> 2;
    int q = t & 3;

    float s1i = g_s1 [head * N_NODES + i0 + m];
    float e1i = g_e1i[head * N_NODES + i0 + m];
    float e2i = g_e2i[head * N_NODES + i0 + m];
    float dsum = 0.f;

    // MMA identity: warp -> (row group mw of 16, col group nw of 32)
    int mw = warp & 3;
    int nw = warp >> 2;
    float acc[4][4];
    #pragma unroll
    for (int a = 0; a < 4; a++)
        #pragma unroll
        for (int b = 0; b < 4; b++) acc[a][b] = 0.f;

    const int*   adjrow = adj + (size_t)(i0 + m) * N_NODES;
    const float* s2p = g_s2  + head * N_NODES;
    const float* e1p = g_e1j + head * N_NODES;
    const float* e2p = g_e2j + head * N_NODES;
    const float* vbase = g_h + head * HD;

    int vr = t >> 4;          // V-load: row within 16-row group
    int vc = (t & 15) * 4;    // V-load: 4-col group

    for (int j0 = 0; j0 < N_NODES; j0 += TJ) {
        // ---- build P tile (tf32-quantized) + denominator partial ----
        #pragma unroll
        for (int u = 0; u < 4; u++) {
            int jc = q * 16 + u * 4;
            int j  = j0 + jc;
            int4   av  = *(const int4*)  (adjrow + j);
            float4 s2v = *(const float4*)(s2p + j);
            float4 e1v = *(const float4*)(e1p + j);
            float4 e2v = *(const float4*)(e2p + j);
            float w0 = (av.x > 0) ? ((s1i + s2v.x > 0.f) ? e1i * e1v.x : e2i * e2v.x) : 0.f;
            float w1 = (av.y > 0) ? ((s1i + s2v.y > 0.f) ? e1i * e1v.y : e2i * e2v.y) : 0.f;
            float w2 = (av.z > 0) ? ((s1i + s2v.z > 0.f) ? e1i * e1v.z : e2i * e2v.z) : 0.f;
            float w3 = (av.w > 0) ? ((s1i + s2v.w > 0.f) ? e1i * e1v.w : e2i * e2v.w) : 0.f;
            w0 = __uint_as_float(f2tf32(w0));
            w1 = __uint_as_float(f2tf32(w1));
            w2 = __uint_as_float(f2tf32(w2));
            w3 = __uint_as_float(f2tf32(w3));
            *(float4*)(Psh + m * PST + jc) = make_float4(w0, w1, w2, w3);
            dsum += (w0 + w1) + (w2 + w3);
        }

        // ---- load V tile [j'][d] for this head, rna-rounded to tf32 ----
        const float* vb = vbase + (size_t)j0 * HID;
        #pragma unroll
        for (int u = 0; u < 4; u++) {
            int jr = u * 16 + vr;
            float4 v = *(const float4*)(vb + (size_t)jr * HID + vc);
            *(float4*)(Vsh + jr * VST + vc) = make_float4(
                __uint_as_float(f2tf32(v.x)), __uint_as_float(f2tf32(v.y)),
                __uint_as_float(f2tf32(v.z)), __uint_as_float(f2tf32(v.w)));
        }
        __syncthreads();

        // ---- MMA: acc += P[mw*16 : +16][:] @ V[:][nw*32 : +32] ----
        const float* Pb = Psh + (mw * 16) * PST;
        const float* Vb = Vsh + nw * 32;
        int r = lane >> 2, c = lane & 3;
        #pragma unroll
        for (int k = 0; k < TJ; k += 8) {
            unsigned a0 = __float_as_uint(Pb[(r    ) * PST + k + c    ]);
            unsigned a1 = __float_as_uint(Pb[(r + 8) * PST + k + c    ]);
            unsigned a2 = __float_as_uint(Pb[(r    ) * PST + k + c + 4]);
            unsigned a3 = __float_as_uint(Pb[(r + 8) * PST + k + c + 4]);
            #pragma unroll
            for (int nt = 0; nt < 4; nt++) {
                unsigned b0 = __float_as_uint(Vb[(k + c    ) * VST + nt * 8 + r]);
                unsigned b1 = __float_as_uint(Vb[(k + c + 4) * VST + nt * 8 + r]);
                asm volatile(
                    "mma.sync.aligned.m16n8k8.row.col.f32.tf32.tf32.f32 "
                    "{%0,%1,%2,%3}, {%4,%5,%6,%7}, {%8,%9}, {%0,%1,%2,%3};\n"
                    : "+f"(acc[nt][0]), "+f"(acc[nt][1]),
                      "+f"(acc[nt][2]), "+f"(acc[nt][3])
                    : "r"(a0), "r"(a1), "r"(a2), "r"(a3), "r"(b0), "r"(b1));
            }
        }
        __syncthreads();
    }

    // ---- row denominators: reduce over column-quarters q (lane bits 0-1) ----
    dsum += __shfl_xor_sync(0xffffffffu, dsum, 1);
    dsum += __shfl_xor_sync(0xffffffffu, dsum, 2);
    if (q == 0) dsh[m] = dsum;
    __syncthreads();

    // ---- normalize + write ----
    int r = lane >> 2, c2 = (lane & 3) * 2;
    float inv0 = 1.f / dsh[mw * 16 + r];
    float inv1 = 1.f / dsh[mw * 16 + r + 8];
    #pragma unroll
    for (int nt = 0; nt < 4; nt++) {
        int col  = head * HD + nw * 32 + nt * 8 + c2;
        int row0 = i0 + mw * 16 + r;
        *(float2*)(out + (size_t)row0 * HID + col) =
            make_float2(acc[nt][0] * inv0, acc[nt][1] * inv0);
        *(float2*)(out + (size_t)(row0 + 8) * HID + col) =
            make_float2(acc[nt][2] * inv1, acc[nt][3] * inv1);
    }
}

// ---------------- launch ----------------
extern "C" void kernel_launch(void* const* d_in, const int* in_sizes, int n_in,
                              void* d_out, int out_size) {
    const float* x   = (const float*)d_in[0];   // [4096, 256]
    const int*   adj = (const int*)  d_in[1];   // [4096, 4096]
    const float* W   = (const float*)d_in[2];   // [256, 256]
    const float* a1  = (const float*)d_in[3];   // [64]
    const float* a2  = (const float*)d_in[4];   // [64]
    float* out = (float*)d_out;                 // [4096, 256]

    float* h_ptr;
    cudaGetSymbolAddress((void**)&h_ptr, g_h);

    dim3 ggrid(N_NODES / 64, HID / 64);
    gemm_hw<<<ggrid, 256>>>(x, W, h_ptr);

    scores_kernel<<<(N_NODES * NH * 32) / 256, 256>>>(a1, a2);

    attn_mma<<<dim3(N_NODES / TM, NH), 256>>>(adj, out);
}